// round 4
// baseline (speedup 1.0000x reference)
#include <cuda_runtime.h>
#include <cstdint>
#include <cstddef>

// 2-layer LSTM: B=32, T=512, IN=2048, H=512, fp32.
// Pipeline: [reset] gemm0 -> rec0 -> [reset] gemm1 -> rec1 (all graph-capturable).

typedef unsigned long long ull;

#define Bb 32
#define Tt 512
#define Hh 512
#define Gg 2048          // 4*H
#define Mm 16384         // B*T
#define HSS 516          // padded smem row stride (floats), 16B-aligned, conflict-free

// ---- device scratch (no allocations allowed) -------------------------------
__device__ float g_xgt[(size_t)Tt * Gg * Bb];   // [t][g][b]  128 MB (reused by both layers)
__device__ float g_h1[(size_t)Mm * Hh];         // layer-0 output sequence [b*T+t][u]
__device__ float g_ht[2][Bb * Hh];              // double-buffered hidden state [buf][b][u]
__device__ unsigned g_bar;

// ---- packed f32x2 helpers (FFMA2 only reachable via PTX) -------------------
__device__ __forceinline__ ull pk(float x, float y) {
    ull r; asm("mov.b64 %0,{%1,%2};" : "=l"(r) : "f"(x), "f"(y)); return r;
}
__device__ __forceinline__ void upk(ull v, float& x, float& y) {
    asm("mov.b64 {%0,%1},%2;" : "=f"(x), "=f"(y) : "l"(v));
}
__device__ __forceinline__ void fma2(ull& d, ull a, ull b) {
    asm("fma.rn.f32x2 %0,%1,%2,%0;" : "+l"(d) : "l"(a), "l"(b));
}
__device__ __forceinline__ float sigf(float x) { return 1.f / (1.f + __expf(-x)); }
__device__ __forceinline__ float tanh_f(float x) {
    float a = fabsf(x);
    float e = __expf(-2.f * a);            // in (0,1]: overflow-safe
    float t = (1.f - e) / (1.f + e);
    return copysignf(t, x);
}

__global__ void reset_bar() { g_bar = 0u; }

// ============================================================================
// GEMM: g_xgt[t][g][b] = A[m][k] @ W[g][k]^T + (b1[g]+b2[g]),  m = b*T+t
// BM=128, BN=64, BK=16, 256 threads, 8x4 per-thread tile, f32x2 accumulation.
// M=16384, N=2048 fixed; K is 2048 (layer 0) or 512 (layer 1). All divisible.
// ============================================================================
#define BM 128
#define BN 64
#define BK 16

__global__ __launch_bounds__(256) void gemm_bias(
    const float* __restrict__ A, const float* __restrict__ W,
    const float* __restrict__ b1, const float* __restrict__ b2, int K)
{
    __shared__ float As[BK][BM + 4];
    __shared__ float Bs[BK][BN + 4];
    const int tid = threadIdx.x;
    const int m0 = blockIdx.x * BM;     // x = m-tile (wave covers all b for L2 write merge)
    const int n0 = blockIdx.y * BN;
    const int tx = tid & 15;            // n-frag base = tx*4
    const int ty = tid >> 4;            // m-frag base = ty*8

    ull acc[8][2];
    #pragma unroll
    for (int i = 0; i < 8; i++) { acc[i][0] = 0ull; acc[i][1] = 0ull; }

    for (int kt = 0; kt < K; kt += BK) {
        #pragma unroll
        for (int r = 0; r < 2; r++) {               // A tile: 512 float4
            int f = tid + r * 256;
            int m = f >> 2, k4 = (f & 3) * 4;
            float4 v = *(const float4*)(A + (size_t)(m0 + m) * K + kt + k4);
            As[k4 + 0][m] = v.x; As[k4 + 1][m] = v.y;
            As[k4 + 2][m] = v.z; As[k4 + 3][m] = v.w;
        }
        {                                            // B tile: 256 float4
            int n = tid >> 2, k4 = (tid & 3) * 4;
            float4 v = *(const float4*)(W + (size_t)(n0 + n) * K + kt + k4);
            Bs[k4 + 0][n] = v.x; Bs[k4 + 1][n] = v.y;
            Bs[k4 + 2][n] = v.z; Bs[k4 + 3][n] = v.w;
        }
        __syncthreads();
        #pragma unroll
        for (int kk = 0; kk < BK; kk++) {
            float4 a0 = *(const float4*)&As[kk][ty * 8];
            float4 a1 = *(const float4*)&As[kk][ty * 8 + 4];
            ulonglong2 bv = *(const ulonglong2*)&Bs[kk][tx * 4];  // pre-packed pairs
            float av[8] = {a0.x, a0.y, a0.z, a0.w, a1.x, a1.y, a1.z, a1.w};
            #pragma unroll
            for (int i = 0; i < 8; i++) {
                ull d = pk(av[i], av[i]);
                fma2(acc[i][0], d, bv.x);
                fma2(acc[i][1], d, bv.y);
            }
        }
        __syncthreads();
    }

    float bias[4];
    #pragma unroll
    for (int c = 0; c < 4; c++) { int g = n0 + tx * 4 + c; bias[c] = b1[g] + b2[g]; }
    #pragma unroll
    for (int i = 0; i < 8; i++) {
        int m = m0 + ty * 8 + i;
        int b = m >> 9, t = m & 511;                // m = b*512 + t
        #pragma unroll
        for (int j = 0; j < 2; j++) {
            float v0, v1; upk(acc[i][j], v0, v1);
            int g = n0 + tx * 4 + j * 2;
            g_xgt[((size_t)t * Gg + g) * Bb + b]     = v0 + bias[j * 2];
            g_xgt[((size_t)t * Gg + g + 1) * Bb + b] = v1 + bias[j * 2 + 1];
        }
    }
}

// ============================================================================
// Persistent recurrence: 128 blocks x 256 threads, grid barrier per step.
// Block owns units u0..u0+3 (all 4 gates). Warp w: gate=w>>1, units (w&1)*2,+1.
// Lane = batch. W slice packed f32x2 in smem; h staged to smem each step.
// ============================================================================
#define SMEM_REC (8 * Hh * 8 + Bb * HSS * 4 + 16 * Bb * 4 + 4 * Bb * 4)

__global__ __launch_bounds__(256) void lstm_rec(
    const float* __restrict__ Whh, float* __restrict__ hseq)
{
    extern __shared__ char smraw[];
    ull*   w_s  = (ull*)smraw;                         // [8][512]  32 KB
    float* h_s  = (float*)(smraw + 8 * Hh * 8);        // [32][516] 66 KB
    float* gt_s = h_s + Bb * HSS;                      // [4 gates][4 units][32 b]
    float* c_s  = gt_s + 16 * Bb;                      // [4 units][32 b]

    const int tid  = threadIdx.x;
    const int w    = tid >> 5;
    const int lane = tid & 31;                         // = batch b
    const int u0   = blockIdx.x * 4;
    const int gate = w >> 1;
    const int j0   = (w & 1) * 2;
    const int gr0  = gate * Hh + u0 + j0;              // rows gr0, gr0+1

    // Pack this warp's two W_hh rows into smem as f32x2 pairs.
    for (int k = lane; k < Hh; k += 32)
        w_s[w * Hh + k] = pk(Whh[(size_t)gr0 * Hh + k], Whh[(size_t)(gr0 + 1) * Hh + k]);
    if (w < 4) c_s[w * 32 + lane] = 0.f;
    if (tid < 128) g_ht[0][(tid & 31) * Hh + u0 + (tid >> 5)] = 0.f;  // zero own slice
    __threadfence();
    __syncthreads();

    unsigned bi = 0;
    if (tid == 0) {                                    // barrier 0: zeros visible
        atomicAdd(&g_bar, 1u);
        while (*(volatile unsigned*)&g_bar < 128u * (bi + 1)) {}
        __threadfence();
    }
    bi++;
    __syncthreads();

    for (int t = 0; t < Tt; t++) {
        // Prefetch this warp's xg pair (coalesced over lanes).
        const size_t xo = ((size_t)t * Gg + gr0) * Bb + lane;
        float xv0 = __ldg(g_xgt + xo);
        float xv1 = __ldg(g_xgt + xo + Bb);

        // Stage h (previous step) into smem; must bypass L1 (written by other SMs).
        const float* hb = g_ht[t & 1];
        for (int idx = tid; idx < (Bb * Hh / 4); idx += 256) {
            int b  = idx >> 7;                         // 128 float4 per batch row
            int u4 = (idx & 127) * 4;
            float4 v = __ldcg((const float4*)(hb + b * Hh + u4));
            *(float4*)(h_s + b * HSS + u4) = v;
        }
        __syncthreads();

        // acc = xg + sum_k h[b][k] * {W[gr0][k], W[gr0+1][k]}
        ull acc = pk(xv0, xv1);
        const float* hr = h_s + lane * HSS;
        const ull*   wp = w_s + w * Hh;
        #pragma unroll 4
        for (int k = 0; k < Hh; k += 4) {
            float4 hv = *(const float4*)(hr + k);
            fma2(acc, pk(hv.x, hv.x), wp[k]);
            fma2(acc, pk(hv.y, hv.y), wp[k + 1]);
            fma2(acc, pk(hv.z, hv.z), wp[k + 2]);
            fma2(acc, pk(hv.w, hv.w), wp[k + 3]);
        }
        float p0, p1; upk(acc, p0, p1);
        gt_s[(gate * 4 + j0) * 32 + lane]     = p0;
        gt_s[(gate * 4 + j0 + 1) * 32 + lane] = p1;
        __syncthreads();

        // Pointwise cell update: warp j (0..3) handles unit u0+j, lane = batch.
        if (w < 4) {
            int j = w;
            float iv = sigf(gt_s[(0 * 4 + j) * 32 + lane]);
            float fv = sigf(gt_s[(1 * 4 + j) * 32 + lane]);
            float gv = tanh_f(gt_s[(2 * 4 + j) * 32 + lane]);
            float ov = sigf(gt_s[(3 * 4 + j) * 32 + lane]);
            float c  = fv * c_s[j * 32 + lane] + iv * gv;
            c_s[j * 32 + lane] = c;
            float h = ov * tanh_f(c);
            hseq[((size_t)lane * Tt + t) * Hh + u0 + j] = h;       // [B][T][H]
            g_ht[(t + 1) & 1][lane * Hh + u0 + j] = h;             // next step's state
        }
        __threadfence();
        __syncthreads();
        if (tid == 0) {                                            // grid barrier
            atomicAdd(&g_bar, 1u);
            unsigned tgt = 128u * (bi + 1);
            while (*(volatile unsigned*)&g_bar < tgt) {}
            __threadfence();
        }
        bi++;
        __syncthreads();
    }
}

// ============================================================================
extern "C" void kernel_launch(void* const* d_in, const int* in_sizes, int n_in,
                              void* d_out, int out_size)
{
    const float* feats = (const float*)d_in[0];
    const float* Wih0  = (const float*)d_in[1];
    const float* Whh0  = (const float*)d_in[2];
    const float* bih0  = (const float*)d_in[3];
    const float* bhh0  = (const float*)d_in[4];
    const float* Wih1  = (const float*)d_in[5];
    const float* Whh1  = (const float*)d_in[6];
    const float* bih1  = (const float*)d_in[7];
    const float* bhh1  = (const float*)d_in[8];
    float* out = (float*)d_out;

    cudaFuncSetAttribute(lstm_rec, cudaFuncAttributeMaxDynamicSharedMemorySize, SMEM_REC);

    float* h1_ptr = nullptr;
    cudaGetSymbolAddress((void**)&h1_ptr, g_h1);

    dim3 ggrid(Mm / BM, Gg / BN);  // (128, 32)

    // Layer 0
    gemm_bias<<<ggrid, 256>>>(feats, Wih0, bih0, bhh0, 2048);
    reset_bar<<<1, 1>>>();
    lstm_rec<<<128, 256, SMEM_REC>>>(Whh0, h1_ptr);

    // Layer 1
    gemm_bias<<<ggrid, 256>>>(h1_ptr, Wih1, bih1, bhh1, 512);
    reset_bar<<<1, 1>>>();
    lstm_rec<<<128, 256, SMEM_REC>>>(Whh1, out);
}

// round 5
// speedup vs baseline: 1.2925x; 1.2925x over previous
#include <cuda_runtime.h>
#include <cstdint>
#include <cstddef>

// 2-layer LSTM: B=32, T=512, IN=2048, H=512, fp32.
// Pipeline: gemm0 -> [reset] rec0 -> gemm1 -> [reset] rec1 (graph-capturable).

typedef unsigned long long ull;

#define Bb 32
#define Tt 512
#define Hh 512
#define Gg 2048          // 4*H
#define Mm 16384         // B*T
#define NBLK 128u

// ---- device scratch (no allocations allowed) -------------------------------
__device__ float g_xgt[(size_t)Tt * Gg * Bb];   // [t][g][b]  128 MB (reused)
__device__ float g_h1[(size_t)Mm * Hh];         // layer-0 output [b*T+t][u]
__device__ float g_ht[2][Hh * Bb];              // hidden state, layout [u][b]
__device__ unsigned g_bar;
__device__ volatile unsigned g_rel;

// ---- packed f32x2 helpers --------------------------------------------------
__device__ __forceinline__ ull pk(float x, float y) {
    ull r; asm("mov.b64 %0,{%1,%2};" : "=l"(r) : "f"(x), "f"(y)); return r;
}
__device__ __forceinline__ void upk(ull v, float& x, float& y) {
    asm("mov.b64 {%0,%1},%2;" : "=f"(x), "=f"(y) : "l"(v));
}
__device__ __forceinline__ void fma2(ull& d, ull a, ull b) {
    asm("fma.rn.f32x2 %0,%1,%2,%0;" : "+l"(d) : "l"(a), "l"(b));
}
__device__ __forceinline__ ull add2(ull a, ull b) {
    ull r; asm("add.rn.f32x2 %0,%1,%2;" : "=l"(r) : "l"(a), "l"(b)); return r;
}
__device__ __forceinline__ float sigf(float x) { return 1.f / (1.f + __expf(-x)); }
__device__ __forceinline__ float tanh_f(float x) {
    float a = fabsf(x);
    float e = __expf(-2.f * a);
    float t = (1.f - e) / (1.f + e);
    return copysignf(t, x);
}

__global__ void reset_bar() { g_bar = 0u; g_rel = 0u; }

// ============================================================================
// GEMM: g_xgt[t][g][b] = A[m][k] @ W[g][k]^T + (b1[g]+b2[g]),  m = b*T+t
// (unchanged from the passing R3 kernel)
// ============================================================================
#define BM 128
#define BN 64
#define BK 16

__global__ __launch_bounds__(256) void gemm_bias(
    const float* __restrict__ A, const float* __restrict__ W,
    const float* __restrict__ b1, const float* __restrict__ b2, int K)
{
    __shared__ float As[BK][BM + 4];
    __shared__ float Bs[BK][BN + 4];
    const int tid = threadIdx.x;
    const int m0 = blockIdx.x * BM;
    const int n0 = blockIdx.y * BN;
    const int tx = tid & 15;
    const int ty = tid >> 4;

    ull acc[8][2];
    #pragma unroll
    for (int i = 0; i < 8; i++) { acc[i][0] = 0ull; acc[i][1] = 0ull; }

    for (int kt = 0; kt < K; kt += BK) {
        #pragma unroll
        for (int r = 0; r < 2; r++) {
            int f = tid + r * 256;
            int m = f >> 2, k4 = (f & 3) * 4;
            float4 v = *(const float4*)(A + (size_t)(m0 + m) * K + kt + k4);
            As[k4 + 0][m] = v.x; As[k4 + 1][m] = v.y;
            As[k4 + 2][m] = v.z; As[k4 + 3][m] = v.w;
        }
        {
            int n = tid >> 2, k4 = (tid & 3) * 4;
            float4 v = *(const float4*)(W + (size_t)(n0 + n) * K + kt + k4);
            Bs[k4 + 0][n] = v.x; Bs[k4 + 1][n] = v.y;
            Bs[k4 + 2][n] = v.z; Bs[k4 + 3][n] = v.w;
        }
        __syncthreads();
        #pragma unroll
        for (int kk = 0; kk < BK; kk++) {
            float4 a0 = *(const float4*)&As[kk][ty * 8];
            float4 a1 = *(const float4*)&As[kk][ty * 8 + 4];
            ulonglong2 bv = *(const ulonglong2*)&Bs[kk][tx * 4];
            float av[8] = {a0.x, a0.y, a0.z, a0.w, a1.x, a1.y, a1.z, a1.w};
            #pragma unroll
            for (int i = 0; i < 8; i++) {
                ull d = pk(av[i], av[i]);
                fma2(acc[i][0], d, bv.x);
                fma2(acc[i][1], d, bv.y);
            }
        }
        __syncthreads();
    }

    float bias[4];
    #pragma unroll
    for (int c = 0; c < 4; c++) { int g = n0 + tx * 4 + c; bias[c] = b1[g] + b2[g]; }
    #pragma unroll
    for (int i = 0; i < 8; i++) {
        int m = m0 + ty * 8 + i;
        int b = m >> 9, t = m & 511;
        #pragma unroll
        for (int j = 0; j < 2; j++) {
            float v0, v1; upk(acc[i][j], v0, v1);
            int g = n0 + tx * 4 + j * 2;
            g_xgt[((size_t)t * Gg + g) * Bb + b]     = v0 + bias[j * 2];
            g_xgt[((size_t)t * Gg + g + 1) * Bb + b] = v1 + bias[j * 2 + 1];
        }
    }
}

// ============================================================================
// Persistent recurrence: 128 blocks x 256 threads, 1 grid barrier per step.
// Block owns 4 units -> 16 gate rows (r_local = gate*4 + u).
// Warp w: k-chunk kc = w>>1 (128 k each). Lane: batch pair p = lane&15,
// row group rg = (lane>>4) + 2*(w&1); lane computes rows rg*4..rg*4+3 for
// batches 2p, 2p+1 over its k-chunk. Partials reduced through smem.
// smem: h2[16 pairs][514] ull, w4[16 rows][514] ull (w duplicated), part 8KB.
// ============================================================================
#define HS2 514
#define SM_H2   (16 * HS2 * 8)          // 65792
#define SM_W4   (16 * HS2 * 8)          // 65792
#define SM_PART (4 * 16 * 16 * 8)       // 8192
#define SMEM_REC (SM_H2 + SM_W4 + SM_PART)

__global__ __launch_bounds__(256) void lstm_rec(
    const float* __restrict__ Whh, float* __restrict__ hseq)
{
    extern __shared__ char smraw[];
    ull* h2 = (ull*)smraw;                       // [p][k]  pair (h[2p][k],h[2p+1][k])
    ull* w4 = (ull*)(smraw + SM_H2);             // [r][k]  pair (w,w)
    ull* part = (ull*)(smraw + SM_H2 + SM_W4);   // [kc][r][p]
    float* partf = (float*)part;

    const int tid  = threadIdx.x;
    const int w    = tid >> 5;
    const int lane = tid & 31;
    const int u0   = blockIdx.x * 4;

    const int kc = w >> 1;
    const int p  = lane & 15;
    const int rg = (lane >> 4) + 2 * (w & 1);
    const int k0 = kc * 128;

    // ---- init: pack W_hh rows (duplicated pairs) into smem ----
    for (int i = tid; i < 16 * Hh; i += 256) {
        int r = i >> 9, k = i & 511;
        int gr = (r >> 2) * Hh + u0 + (r & 3);
        float v = Whh[(size_t)gr * Hh + k];
        w4[r * HS2 + k] = pk(v, v);
    }
    // zero own slice of h state (layout [u][b])
    if (tid < 128) g_ht[0][(u0 + (tid >> 5)) * Bb + (tid & 31)] = 0.f;

    // pointwise ownership: thread (tid<128) owns unit pu, batch pb; c in register
    const int pu = tid >> 5;
    const int pb = tid & 31;
    float c = 0.f;

    __syncthreads();
    unsigned bi = 1;
    if (tid == 0) {                              // barrier 0: zeros visible
        __threadfence();
        unsigned old = atomicAdd(&g_bar, 1u);
        if (old == NBLK * bi - 1u) g_rel = bi;
        while (g_rel < bi) {}
        __threadfence();
    }
    __syncthreads();
    bi++;

    for (int t = 0; t < Tt; t++) {
        // ---- prefetch xg for pointwise (tid<128: 4 gates) ----
        float xv0 = 0.f, xv1 = 0.f, xv2 = 0.f, xv3 = 0.f;
        if (tid < 128) {
            const float* xb = g_xgt + ((size_t)t * Gg + u0 + pu) * Bb + pb;
            xv0 = __ldg(xb);
            xv1 = __ldg(xb + (size_t)Hh * Bb);
            xv2 = __ldg(xb + (size_t)2 * Hh * Bb);
            xv3 = __ldg(xb + (size_t)3 * Hh * Bb);
        }

        // ---- stage h[u][b] (64KB) -> h2[p][k] pairs ----
        const float* hb = g_ht[t & 1];
        #pragma unroll
        for (int j = 0; j < 16; j++) {
            int i = tid + j * 256;               // float4 index, 4096 total
            int k = i >> 3, pp = i & 7;          // 8 float4 per k-row
            float4 v = __ldcg((const float4*)(hb + k * Bb + pp * 4));
            h2[(2 * pp)     * HS2 + k] = pk(v.x, v.y);
            h2[(2 * pp + 1) * HS2 + k] = pk(v.z, v.w);
        }
        __syncthreads();

        // ---- partial dot products: 4 rows x 2 batches x 128 k per lane ----
        ull a0e = 0, a0o = 0, a1e = 0, a1o = 0;
        ull a2e = 0, a2o = 0, a3e = 0, a3o = 0;
        const ull* hp  = h2 + p * HS2 + k0;
        const ull* wp0 = w4 + (rg * 4 + 0) * HS2 + k0;
        const ull* wp1 = w4 + (rg * 4 + 1) * HS2 + k0;
        const ull* wp2 = w4 + (rg * 4 + 2) * HS2 + k0;
        const ull* wp3 = w4 + (rg * 4 + 3) * HS2 + k0;
        #pragma unroll 4
        for (int kk = 0; kk < 128; kk += 2) {
            ulonglong2 hv = *(const ulonglong2*)(hp + kk);
            ulonglong2 w0 = *(const ulonglong2*)(wp0 + kk);
            ulonglong2 w1 = *(const ulonglong2*)(wp1 + kk);
            ulonglong2 w2 = *(const ulonglong2*)(wp2 + kk);
            ulonglong2 w3 = *(const ulonglong2*)(wp3 + kk);
            fma2(a0e, hv.x, w0.x); fma2(a0o, hv.y, w0.y);
            fma2(a1e, hv.x, w1.x); fma2(a1o, hv.y, w1.y);
            fma2(a2e, hv.x, w2.x); fma2(a2o, hv.y, w2.y);
            fma2(a3e, hv.x, w3.x); fma2(a3o, hv.y, w3.y);
        }
        {
            ull* pb4 = part + ((size_t)kc * 16 + rg * 4) * 16 + p;
            pb4[0]  = add2(a0e, a0o);
            pb4[16] = add2(a1e, a1o);
            pb4[32] = add2(a2e, a2o);
            pb4[48] = add2(a3e, a3o);
        }
        __syncthreads();

        // ---- reduce + activations + cell update (tid<128) ----
        if (tid < 128) {
            float pre[4] = {xv0, xv1, xv2, xv3};
            #pragma unroll
            for (int g = 0; g < 4; g++) {
                int r = g * 4 + pu;
                #pragma unroll
                for (int q = 0; q < 4; q++)
                    pre[g] += partf[(q * 16 + r) * 32 + pb];
            }
            float iv = sigf(pre[0]);
            float fv = sigf(pre[1]);
            float gv = tanh_f(pre[2]);
            float ov = sigf(pre[3]);
            c = fv * c + iv * gv;
            float h = ov * tanh_f(c);
            hseq[((size_t)pb * Tt + t) * Hh + u0 + pu] = h;   // [B][T][H]
            g_ht[(t + 1) & 1][(u0 + pu) * Bb + pb] = h;
        }
        __syncthreads();

        // ---- grid barrier (flag release; single-thread fence) ----
        if (tid == 0) {
            __threadfence();
            unsigned old = atomicAdd(&g_bar, 1u);
            if (old == NBLK * bi - 1u) g_rel = bi;
            while (g_rel < bi) {}
            __threadfence();
        }
        __syncthreads();
        bi++;
    }
}

// ============================================================================
extern "C" void kernel_launch(void* const* d_in, const int* in_sizes, int n_in,
                              void* d_out, int out_size)
{
    const float* feats = (const float*)d_in[0];
    const float* Wih0  = (const float*)d_in[1];
    const float* Whh0  = (const float*)d_in[2];
    const float* bih0  = (const float*)d_in[3];
    const float* bhh0  = (const float*)d_in[4];
    const float* Wih1  = (const float*)d_in[5];
    const float* Whh1  = (const float*)d_in[6];
    const float* bih1  = (const float*)d_in[7];
    const float* bhh1  = (const float*)d_in[8];
    float* out = (float*)d_out;

    cudaFuncSetAttribute(lstm_rec, cudaFuncAttributeMaxDynamicSharedMemorySize, SMEM_REC);

    float* h1_ptr = nullptr;
    cudaGetSymbolAddress((void**)&h1_ptr, g_h1);

    dim3 ggrid(Mm / BM, Gg / BN);  // (128, 32)

    gemm_bias<<<ggrid, 256>>>(feats, Wih0, bih0, bhh0, 2048);
    reset_bar<<<1, 1>>>();
    lstm_rec<<<128, 256, SMEM_REC>>>(Whh0, h1_ptr);

    gemm_bias<<<ggrid, 256>>>(h1_ptr, Wih1, bih1, bhh1, 512);
    reset_bar<<<1, 1>>>();
    lstm_rec<<<128, 256, SMEM_REC>>>(Whh1, out);
}

// round 10
// speedup vs baseline: 1.3644x; 1.0557x over previous
#include <cuda_runtime.h>
#include <cstdint>
#include <cstddef>

// 2-layer LSTM: B=32, T=512, IN=2048, H=512, fp32.
// Pipeline: gemm0 -> [reset] rec0 -> gemm1 -> [reset] rec1 (graph-capturable).

typedef unsigned long long ull;

#define Bb 32
#define Tt 512
#define Hh 512
#define Gg 2048          // 4*H
#define Mm 16384         // B*T
#define NBLK 128u

// ---- device scratch (no allocations allowed) -------------------------------
__device__ float g_xgt[(size_t)Tt * Gg * Bb];   // [t][g][b]  128 MB (reused)
__device__ float g_h1[(size_t)Mm * Hh];         // layer-0 output [b*T+t][u]
__device__ float g_ht[2][Hh * Bb];              // hidden state, layout [u][b] (proven R5-bench)
__device__ unsigned g_bar;
__device__ volatile unsigned g_rel;

// ---- packed f32x2 helpers --------------------------------------------------
__device__ __forceinline__ ull pk(float x, float y) {
    ull r; asm("mov.b64 %0,{%1,%2};" : "=l"(r) : "f"(x), "f"(y)); return r;
}
__device__ __forceinline__ void upk(ull v, float& x, float& y) {
    asm("mov.b64 {%0,%1},%2;" : "=f"(x), "=f"(y) : "l"(v));
}
__device__ __forceinline__ void fma2(ull& d, ull a, ull b) {
    asm("fma.rn.f32x2 %0,%1,%2,%0;" : "+l"(d) : "l"(a), "l"(b));
}
__device__ __forceinline__ float sigf(float x) { return 1.f / (1.f + __expf(-x)); }
__device__ __forceinline__ float tanh_f(float x) {
    float a = fabsf(x);
    float e = __expf(-2.f * a);
    float t = (1.f - e) / (1.f + e);
    return copysignf(t, x);
}

__global__ void reset_bar() { g_bar = 0u; g_rel = 0u; }

// ============================================================================
// GEMM: g_xgt[t][g][b] = A[m][k] @ W[g][k]^T + (b1[g]+b2[g]),  m = b*T+t
// (unchanged — passing since R3; 890us for K=2048)
// ============================================================================
#define BM 128
#define BN 64
#define BK 16

__global__ __launch_bounds__(256) void gemm_bias(
    const float* __restrict__ A, const float* __restrict__ W,
    const float* __restrict__ b1, const float* __restrict__ b2, int K)
{
    __shared__ float As[BK][BM + 4];
    __shared__ float Bs[BK][BN + 4];
    const int tid = threadIdx.x;
    const int m0 = blockIdx.x * BM;
    const int n0 = blockIdx.y * BN;
    const int tx = tid & 15;
    const int ty = tid >> 4;

    ull acc[8][2];
    #pragma unroll
    for (int i = 0; i < 8; i++) { acc[i][0] = 0ull; acc[i][1] = 0ull; }

    for (int kt = 0; kt < K; kt += BK) {
        #pragma unroll
        for (int r = 0; r < 2; r++) {
            int f = tid + r * 256;
            int m = f >> 2, k4 = (f & 3) * 4;
            float4 v = *(const float4*)(A + (size_t)(m0 + m) * K + kt + k4);
            As[k4 + 0][m] = v.x; As[k4 + 1][m] = v.y;
            As[k4 + 2][m] = v.z; As[k4 + 3][m] = v.w;
        }
        {
            int n = tid >> 2, k4 = (tid & 3) * 4;
            float4 v = *(const float4*)(W + (size_t)(n0 + n) * K + kt + k4);
            Bs[k4 + 0][n] = v.x; Bs[k4 + 1][n] = v.y;
            Bs[k4 + 2][n] = v.z; Bs[k4 + 3][n] = v.w;
        }
        __syncthreads();
        #pragma unroll
        for (int kk = 0; kk < BK; kk++) {
            float4 a0 = *(const float4*)&As[kk][ty * 8];
            float4 a1 = *(const float4*)&As[kk][ty * 8 + 4];
            ulonglong2 bv = *(const ulonglong2*)&Bs[kk][tx * 4];
            float av[8] = {a0.x, a0.y, a0.z, a0.w, a1.x, a1.y, a1.z, a1.w};
            #pragma unroll
            for (int i = 0; i < 8; i++) {
                ull d = pk(av[i], av[i]);
                fma2(acc[i][0], d, bv.x);
                fma2(acc[i][1], d, bv.y);
            }
        }
        __syncthreads();
    }

    float bias[4];
    #pragma unroll
    for (int c = 0; c < 4; c++) { int g = n0 + tx * 4 + c; bias[c] = b1[g] + b2[g]; }
    #pragma unroll
    for (int i = 0; i < 8; i++) {
        int m = m0 + ty * 8 + i;
        int b = m >> 9, t = m & 511;
        #pragma unroll
        for (int j = 0; j < 2; j++) {
            float v0, v1; upk(acc[i][j], v0, v1);
            int g = n0 + tx * 4 + j * 2;
            g_xgt[((size_t)t * Gg + g) * Bb + b]     = v0 + bias[j * 2];
            g_xgt[((size_t)t * Gg + g + 1) * Bb + b] = v1 + bias[j * 2 + 1];
        }
    }
}

// ============================================================================
// Persistent recurrence: 128 blocks x 256 threads.
// Barrier: proven R5-bench protocol (all-thread fence; tid0 atomicAdd + g_rel).
// Block owns 4 units -> 16 gate rows. Register blocking:
//   warp w = k-chunk [w*64, w*64+64); lane: p8 = lane&7 handles batch-pairs
//   p8 and p8+8; rg = lane>>3 handles rows rg*4..rg*4+3.
//   Per iter (2 k): 6 LDS.128 feed 16 fma2 (was 5 LDS.128 per 8 fma2).
// Partials [kc=8][r=16][p=16] ull reduced by pointwise threads (q=0..7).
// ============================================================================
#define HS2 514
#define SM_H2   (16 * HS2 * 8)          // 65792
#define SM_W4   (16 * HS2 * 8)          // 65792
#define SM_PART (8 * 16 * 16 * 8)       // 16384
#define SMEM_REC (SM_H2 + SM_W4 + SM_PART)

__global__ __launch_bounds__(256) void lstm_rec(
    const float* __restrict__ Whh, float* __restrict__ hseq)
{
    extern __shared__ char smraw[];
    ull* h2 = (ull*)smraw;                       // [pair p][k]  (h[2p][k],h[2p+1][k])
    ull* w4 = (ull*)(smraw + SM_H2);             // [row r][k]   (w,w)
    ull* part = (ull*)(smraw + SM_H2 + SM_W4);   // [kc][r][p]
    float* partf = (float*)part;

    const int tid  = threadIdx.x;
    const int w    = tid >> 5;
    const int lane = tid & 31;
    const int bid  = blockIdx.x;
    const int u0   = bid * 4;

    const int p8 = lane & 7;                     // batch-pairs p8, p8+8
    const int rg = lane >> 3;                    // rows rg*4 .. rg*4+3
    const int k0 = w * 64;                       // k-chunk per warp

    // ---- init: pack W_hh rows (duplicated pairs) into smem ----
    for (int i = tid; i < 16 * Hh; i += 256) {
        int r = i >> 9, k = i & 511;
        int gr = (r >> 2) * Hh + u0 + (r & 3);
        float v = Whh[(size_t)gr * Hh + k];
        w4[r * HS2 + k] = pk(v, v);
    }
    // zero own slice of h state (layout [u][b])
    if (tid < 128) g_ht[0][(u0 + (tid >> 5)) * Bb + (tid & 31)] = 0.f;

    // pointwise ownership: tid<128 owns unit pu, batch pb; c in register
    const int pu = tid >> 5;
    const int pb = tid & 31;
    float c = 0.f;

    __syncthreads();
    unsigned bi = 1;
    if (tid == 0) {                              // barrier 0: zeros visible
        __threadfence();
        unsigned old = atomicAdd(&g_bar, 1u);
        if (old == NBLK * bi - 1u) g_rel = bi;
        while (g_rel < bi) {}
        __threadfence();
    }
    __syncthreads();
    bi++;

    for (int t = 0; t < Tt; t++) {
        // ---- prefetch xg for pointwise (tid<128: 4 gates) ----
        float xv0 = 0.f, xv1 = 0.f, xv2 = 0.f, xv3 = 0.f;
        if (tid < 128) {
            const float* xb = g_xgt + ((size_t)t * Gg + u0 + pu) * Bb + pb;
            xv0 = __ldg(xb);
            xv1 = __ldg(xb + (size_t)Hh * Bb);
            xv2 = __ldg(xb + (size_t)2 * Hh * Bb);
            xv3 = __ldg(xb + (size_t)3 * Hh * Bb);
        }

        // ---- stage h[u][b] (64KB) -> h2[p][k] pairs (proven R5-bench path) ----
        const float* hb = g_ht[t & 1];
        #pragma unroll
        for (int j = 0; j < 16; j++) {
            int idx = tid + j * 256;             // float4 index, 4096 total
            int k = idx >> 3, pp = idx & 7;      // 8 float4 per unit row
            float4 v = __ldcg((const float4*)(hb + k * Bb + pp * 4));
            h2[(2 * pp)     * HS2 + k] = pk(v.x, v.y);
            h2[(2 * pp + 1) * HS2 + k] = pk(v.z, v.w);
        }
        __syncthreads();

        // ---- partials: 4 rows x 2 pairs (4 batches) x 64 k per lane ----
        ull a00 = 0, a01 = 0, a10 = 0, a11 = 0;
        ull a20 = 0, a21 = 0, a30 = 0, a31 = 0;
        const ull* hp0 = h2 + p8 * HS2 + k0;
        const ull* hp1 = h2 + (p8 + 8) * HS2 + k0;
        const ull* wq0 = w4 + (rg * 4 + 0) * HS2 + k0;
        const ull* wq1 = w4 + (rg * 4 + 1) * HS2 + k0;
        const ull* wq2 = w4 + (rg * 4 + 2) * HS2 + k0;
        const ull* wq3 = w4 + (rg * 4 + 3) * HS2 + k0;
        #pragma unroll 2
        for (int kk = 0; kk < 64; kk += 2) {
            ulonglong2 h0 = *(const ulonglong2*)(hp0 + kk);
            ulonglong2 h1 = *(const ulonglong2*)(hp1 + kk);
            ulonglong2 w0 = *(const ulonglong2*)(wq0 + kk);
            ulonglong2 w1 = *(const ulonglong2*)(wq1 + kk);
            ulonglong2 w2 = *(const ulonglong2*)(wq2 + kk);
            ulonglong2 w3 = *(const ulonglong2*)(wq3 + kk);
            fma2(a00, h0.x, w0.x); fma2(a01, h1.x, w0.x);
            fma2(a10, h0.x, w1.x); fma2(a11, h1.x, w1.x);
            fma2(a20, h0.x, w2.x); fma2(a21, h1.x, w2.x);
            fma2(a30, h0.x, w3.x); fma2(a31, h1.x, w3.x);
            fma2(a00, h0.y, w0.y); fma2(a01, h1.y, w0.y);
            fma2(a10, h0.y, w1.y); fma2(a11, h1.y, w1.y);
            fma2(a20, h0.y, w2.y); fma2(a21, h1.y, w2.y);
            fma2(a30, h0.y, w3.y); fma2(a31, h1.y, w3.y);
        }
        {
            // part[kc=w][r][p]: pp4[j*16] = row rg*4+j pair p8; +8 = pair p8+8
            ull* pp4 = part + ((size_t)w * 16 + rg * 4) * 16 + p8;
            pp4[0]  = a00; pp4[8]  = a01;
            pp4[16] = a10; pp4[24] = a11;
            pp4[32] = a20; pp4[40] = a21;
            pp4[48] = a30; pp4[56] = a31;
        }
        __syncthreads();

        // ---- reduce + activations + cell update (tid<128) ----
        if (tid < 128) {
            float pre[4] = {xv0, xv1, xv2, xv3};
            #pragma unroll
            for (int g = 0; g < 4; g++) {
                int r = g * 4 + pu;
                #pragma unroll
                for (int q = 0; q < 8; q++)
                    pre[g] += partf[(q * 16 + r) * 32 + pb];
            }
            float iv = sigf(pre[0]);
            float fv = sigf(pre[1]);
            float gv = tanh_f(pre[2]);
            float ov = sigf(pre[3]);
            c = fv * c + iv * gv;
            float h = ov * tanh_f(c);
            hseq[((size_t)pb * Tt + t) * Hh + u0 + pu] = h;      // [B][T][H]
            g_ht[(t + 1) & 1][(u0 + pu) * Bb + pb] = h;
        }
        __threadfence();
        __syncthreads();

        // ---- grid barrier (proven R5-bench protocol) ----
        if (tid == 0) {
            __threadfence();
            unsigned old = atomicAdd(&g_bar, 1u);
            if (old == NBLK * bi - 1u) g_rel = bi;
            while (g_rel < bi) {}
            __threadfence();
        }
        __syncthreads();
        bi++;
    }
}

// ============================================================================
extern "C" void kernel_launch(void* const* d_in, const int* in_sizes, int n_in,
                              void* d_out, int out_size)
{
    const float* feats = (const float*)d_in[0];
    const float* Wih0  = (const float*)d_in[1];
    const float* Whh0  = (const float*)d_in[2];
    const float* bih0  = (const float*)d_in[3];
    const float* bhh0  = (const float*)d_in[4];
    const float* Wih1  = (const float*)d_in[5];
    const float* Whh1  = (const float*)d_in[6];
    const float* bih1  = (const float*)d_in[7];
    const float* bhh1  = (const float*)d_in[8];
    float* out = (float*)d_out;

    cudaFuncSetAttribute(lstm_rec, cudaFuncAttributeMaxDynamicSharedMemorySize, SMEM_REC);

    float* h1_ptr = nullptr;
    cudaGetSymbolAddress((void**)&h1_ptr, g_h1);

    dim3 ggrid(Mm / BM, Gg / BN);  // (128, 32)

    gemm_bias<<<ggrid, 256>>>(feats, Wih0, bih0, bhh0, 2048);
    reset_bar<<<1, 1>>>();
    lstm_rec<<<128, 256, SMEM_REC>>>(Whh0, h1_ptr);

    gemm_bias<<<ggrid, 256>>>(h1_ptr, Wih1, bih1, bhh1, 512);
    reset_bar<<<1, 1>>>();
    lstm_rec<<<128, 256, SMEM_REC>>>(Whh1, out);
}